// round 13
// baseline (speedup 1.0000x reference)
#include <cuda_runtime.h>
#include <cuda_bf16.h>
#include <mma.h>
#include <cstdint>

using namespace nvcuda;

#define N_NODES_MAX 50000
#define N_EDGES_MAX 800000
#define F_IN 256
#define H_DIM 128

// ---------------------------------------------------------------------------
// Scratch (__device__ globals; no cudaMalloc allowed)
// ---------------------------------------------------------------------------
__device__ float g_s1 [N_NODES_MAX * H_DIM];
__device__ float g_h1 [N_NODES_MAX * H_DIM];
__device__ int   g_counts [N_NODES_MAX];
__device__ int   g_rowstart[N_NODES_MAX + 1];
__device__ int   g_cursor [N_NODES_MAX];
__device__ int   g_csr_col[N_EDGES_MAX];
__device__ float g_csr_val[N_EDGES_MAX];

// ---------------------------------------------------------------------------
// CSR build
// ---------------------------------------------------------------------------
__global__ void zero_counts(int* __restrict__ counts, int n) {
    int i = blockIdx.x * blockDim.x + threadIdx.x;
    int stride = gridDim.x * blockDim.x;
    for (; i < n; i += stride) counts[i] = 0;
}

// 4-way unrolled histogram: 4 independent atomics in flight per thread.
__global__ void hist_rows(const int* __restrict__ rows, int* __restrict__ counts,
                          int n_edges) {
    int base = (blockIdx.x * blockDim.x + threadIdx.x) * 4;
    int stride = gridDim.x * blockDim.x * 4;
    for (int i = base; i < n_edges; i += stride) {
        int n = min(4, n_edges - i);
        int r[4];
        #pragma unroll
        for (int j = 0; j < 4; j++) if (j < n) r[j] = __ldg(rows + i + j);
        #pragma unroll
        for (int j = 0; j < 4; j++) if (j < n) atomicAdd(&counts[r[j]], 1);
    }
}

__global__ __launch_bounds__(1024) void scan_counts(
    const int* __restrict__ counts, int* __restrict__ row_start,
    int* __restrict__ cursor, int n, int n_edges)
{
    __shared__ int ssum[1024];
    int tid = threadIdx.x;
    int chunk = (n + 1023) / 1024;
    int begin = tid * chunk;
    int end = min(begin + chunk, n);

    int s = 0;
    for (int i = begin; i < end; i++) s += counts[i];
    ssum[tid] = s;
    __syncthreads();

    #pragma unroll
    for (int off = 1; off < 1024; off <<= 1) {
        int v = (tid >= off) ? ssum[tid - off] : 0;
        __syncthreads();
        ssum[tid] += v;
        __syncthreads();
    }

    int offset = (tid == 0) ? 0 : ssum[tid - 1];
    for (int i = begin; i < end; i++) {
        row_start[i] = offset;
        cursor[i]    = offset;
        offset += counts[i];
    }
    if (tid == 0) row_start[n] = n_edges;
}

// 4-way unrolled CSR fill: batch loads, 4 atomics in flight, batch stores.
__global__ void fill_csr(const int* __restrict__ rows, const int* __restrict__ cols,
                         const float* __restrict__ vals, int* __restrict__ cursor,
                         int* __restrict__ csr_col, float* __restrict__ csr_val,
                         int n_edges)
{
    int base = (blockIdx.x * blockDim.x + threadIdx.x) * 4;
    int stride = gridDim.x * blockDim.x * 4;
    for (int i = base; i < n_edges; i += stride) {
        int n = min(4, n_edges - i);
        int r[4], c[4], p[4];
        float v[4];
        #pragma unroll
        for (int j = 0; j < 4; j++) if (j < n) {
            r[j] = __ldg(rows + i + j);
            c[j] = __ldg(cols + i + j);
            v[j] = __ldg(vals + i + j);
        }
        #pragma unroll
        for (int j = 0; j < 4; j++) if (j < n)
            p[j] = atomicAdd(&cursor[r[j]], 1);
        #pragma unroll
        for (int j = 0; j < 4; j++) if (j < n) {
            csr_col[p[j]] = c[j];
            csr_val[p[j]] = v[j];
        }
    }
}

// ---------------------------------------------------------------------------
// TF32 WMMA GEMM: C[M,128] = A[M,K] @ B[K,128]
// tf32 conversion happens once at smem-store time (not per-fragment).
// Block 128x128, 8 warps 2x4; warp 64x32 via 4x2 of 16x16x8. BK=32.
// ---------------------------------------------------------------------------
__global__ __launch_bounds__(256) void sgemm_tf32_n128(
    const float* __restrict__ A, const float* __restrict__ B,
    float* __restrict__ C, int M, int K)
{
    const int BKC = 32;
    __shared__ float As[128][36];
    __shared__ float Bs[32][128];

    int tid = threadIdx.x;
    int warp_id = tid >> 5;
    int warp_row = warp_id & 1;
    int warp_col = warp_id >> 1;
    int block_row = blockIdx.x * 128;

    wmma::fragment<wmma::accumulator, 16, 16, 8, float> c_frag[4][2];
    #pragma unroll
    for (int tr = 0; tr < 4; tr++)
        #pragma unroll
        for (int tc = 0; tc < 2; tc++)
            wmma::fill_fragment(c_frag[tr][tc], 0.0f);

    for (int k0 = 0; k0 < K; k0 += BKC) {
        #pragma unroll
        for (int i = 0; i < 4; i++) {
            int idx = tid + i * 256;
            int arow = idx >> 3;
            int acol = (idx & 7) * 4;
            float4 av = make_float4(0.f, 0.f, 0.f, 0.f);
            if (block_row + arow < M)
                av = *(const float4*)(A + (size_t)(block_row + arow) * K + k0 + acol);
            av.x = wmma::__float_to_tf32(av.x);
            av.y = wmma::__float_to_tf32(av.y);
            av.z = wmma::__float_to_tf32(av.z);
            av.w = wmma::__float_to_tf32(av.w);
            *(float4*)&As[arow][acol] = av;

            int brow = idx >> 5;
            int bcol = (idx & 31) * 4;
            float4 bv = *(const float4*)(B + (size_t)(k0 + brow) * 128 + bcol);
            bv.x = wmma::__float_to_tf32(bv.x);
            bv.y = wmma::__float_to_tf32(bv.y);
            bv.z = wmma::__float_to_tf32(bv.z);
            bv.w = wmma::__float_to_tf32(bv.w);
            *(float4*)&Bs[brow][bcol] = bv;
        }
        __syncthreads();

        #pragma unroll
        for (int ks = 0; ks < 4; ks++) {
            wmma::fragment<wmma::matrix_b, 16, 16, 8, wmma::precision::tf32,
                           wmma::row_major> b_frag[2];
            #pragma unroll
            for (int tc = 0; tc < 2; tc++)
                wmma::load_matrix_sync(b_frag[tc],
                    &Bs[ks * 8][warp_col * 32 + tc * 16], 128);
            #pragma unroll
            for (int tr = 0; tr < 4; tr++) {
                wmma::fragment<wmma::matrix_a, 16, 16, 8, wmma::precision::tf32,
                               wmma::row_major> a_frag;
                wmma::load_matrix_sync(a_frag,
                    &As[warp_row * 64 + tr * 16][ks * 8], 36);
                #pragma unroll
                for (int tc = 0; tc < 2; tc++)
                    wmma::mma_sync(c_frag[tr][tc], a_frag, b_frag[tc],
                                   c_frag[tr][tc]);
            }
        }
        __syncthreads();
    }

    #pragma unroll
    for (int tr = 0; tr < 4; tr++) {
        int grow = block_row + warp_row * 64 + tr * 16;
        if (grow < M) {
            #pragma unroll
            for (int tc = 0; tc < 2; tc++)
                wmma::store_matrix_sync(
                    C + (size_t)grow * 128 + warp_col * 32 + tc * 16,
                    c_frag[tr][tc], 128, wmma::mem_row_major);
        }
    }
}

// ---------------------------------------------------------------------------
// Gather SpMM + bias + relu (one warp per row, float4 lanes, unroll 4)
// ---------------------------------------------------------------------------
__global__ __launch_bounds__(256) void spmm_gather_bias_relu(
    const float* __restrict__ x, const int* __restrict__ row_start,
    const int* __restrict__ csr_col, const float* __restrict__ csr_val,
    const float* __restrict__ bias, float* __restrict__ out, int n_rows)
{
    int warp = (blockIdx.x * blockDim.x + threadIdx.x) >> 5;
    int lane = threadIdx.x & 31;
    if (warp >= n_rows) return;

    int s = row_start[warp];
    int e = row_start[warp + 1];

    const float4* x4 = (const float4*)x;
    float4 acc = make_float4(0.f, 0.f, 0.f, 0.f);

    int i = s;
    for (; i + 4 <= e; i += 4) {
        int   c0 = __ldg(csr_col + i + 0);
        int   c1 = __ldg(csr_col + i + 1);
        int   c2 = __ldg(csr_col + i + 2);
        int   c3 = __ldg(csr_col + i + 3);
        float v0 = __ldg(csr_val + i + 0);
        float v1 = __ldg(csr_val + i + 1);
        float v2 = __ldg(csr_val + i + 2);
        float v3 = __ldg(csr_val + i + 3);
        float4 x0 = __ldg(x4 + (size_t)c0 * 32 + lane);
        float4 x1 = __ldg(x4 + (size_t)c1 * 32 + lane);
        float4 x2 = __ldg(x4 + (size_t)c2 * 32 + lane);
        float4 x3 = __ldg(x4 + (size_t)c3 * 32 + lane);
        acc.x += v0 * x0.x; acc.y += v0 * x0.y; acc.z += v0 * x0.z; acc.w += v0 * x0.w;
        acc.x += v1 * x1.x; acc.y += v1 * x1.y; acc.z += v1 * x1.z; acc.w += v1 * x1.w;
        acc.x += v2 * x2.x; acc.y += v2 * x2.y; acc.z += v2 * x2.z; acc.w += v2 * x2.w;
        acc.x += v3 * x3.x; acc.y += v3 * x3.y; acc.z += v3 * x3.z; acc.w += v3 * x3.w;
    }
    for (; i < e; i++) {
        int   c = __ldg(csr_col + i);
        float v = __ldg(csr_val + i);
        float4 xv = __ldg(x4 + (size_t)c * 32 + lane);
        acc.x += v * xv.x; acc.y += v * xv.y; acc.z += v * xv.z; acc.w += v * xv.w;
    }

    float4 b = __ldg((const float4*)bias + lane);
    float4 o;
    o.x = fmaxf(acc.x + b.x, 0.f);
    o.y = fmaxf(acc.y + b.y, 0.f);
    o.z = fmaxf(acc.z + b.z, 0.f);
    o.w = fmaxf(acc.w + b.w, 0.f);
    ((float4*)out)[(size_t)warp * 32 + lane] = o;
}

// ---------------------------------------------------------------------------
// Launch sequence
// ---------------------------------------------------------------------------
extern "C" void kernel_launch(void* const* d_in, const int* in_sizes, int n_in,
                              void* d_out, int out_size)
{
    const float* features = (const float*)d_in[0];
    const int*   rows     = (const int*)  d_in[1];
    const int*   cols     = (const int*)  d_in[2];
    const float* vals     = (const float*)d_in[3];
    const float* W1       = (const float*)d_in[4];
    const float* b1       = (const float*)d_in[5];
    const float* W2       = (const float*)d_in[6];
    const float* b2       = (const float*)d_in[7];
    float* out = (float*)d_out;

    int M       = in_sizes[0] / F_IN;    // 50000
    int n_edges = in_sizes[1];           // 800000

    float *s1, *h1, *csr_val;
    int *counts, *row_start, *cursor, *csr_col;
    cudaGetSymbolAddress((void**)&s1,        g_s1);
    cudaGetSymbolAddress((void**)&h1,        g_h1);
    cudaGetSymbolAddress((void**)&counts,    g_counts);
    cudaGetSymbolAddress((void**)&row_start, g_rowstart);
    cudaGetSymbolAddress((void**)&cursor,    g_cursor);
    cudaGetSymbolAddress((void**)&csr_col,   g_csr_col);
    cudaGetSymbolAddress((void**)&csr_val,   g_csr_val);

    // --- CSR build (once; reused by both SpMM passes) ---
    zero_counts<<<(M + 255) / 256, 256>>>(counts, M);
    {
        int threads_needed = (n_edges + 3) / 4;
        int blocks = (threads_needed + 255) / 256;   // 782
        hist_rows<<<blocks, 256>>>(rows, counts, n_edges);
        scan_counts<<<1, 1024>>>(counts, row_start, cursor, M, n_edges);
        fill_csr<<<blocks, 256>>>(rows, cols, vals, cursor, csr_col, csr_val,
                                  n_edges);
    }

    int gemm_blocks = (M + 127) / 128;   // 391

    // --- Layer 1 ---
    sgemm_tf32_n128<<<gemm_blocks, 256>>>(features, W1, s1, M, F_IN);
    spmm_gather_bias_relu<<<(M * 32 + 255) / 256, 256>>>(
        s1, row_start, csr_col, csr_val, b1, h1, M);

    // --- Layer 2 ---
    sgemm_tf32_n128<<<gemm_blocks, 256>>>(h1, W2, s1, M, H_DIM);
    spmm_gather_bias_relu<<<(M * 32 + 255) / 256, 256>>>(
        s1, row_start, csr_col, csr_val, b2, out, M);
}